// round 4
// baseline (speedup 1.0000x reference)
#include <cuda_runtime.h>
#include <cstdint>

// ============================================================================
// triu(A @ B), N=4096, fp32 in/out — baseline-sm_100 path (no tcgen05: the
// harness compiles at compute_100).
// mma.sync.m16n8k8 TF32 with 3xTF32 register split (hi*hi + hi*lo + lo*hi)
// -> ~1e-6 rel err. 128x128 CTA tiles; K pruned to [ti*128,(tj+1)*128) by
// triangularity of A and B. Strictly-lower tiles: zero-fill only.
// Round-3 changes: fp32-only smem (35.8KB static __shared__, split to tf32 in
// registers at fragment load) -> no cudaFuncSetAttribute, no static guards,
// fewer LDS (fragments loaded once per k-step, 3 MMA passes from registers).
// ============================================================================

#define N_DIM 4096
#define TILE  128
#define BK    32

// smem float strides (padded for conflict-free LDS/STS)
#define A_STRIDE 36    // 128 rows x 36 floats
#define B_STRIDE 136   // 32 rows x 136 floats
#define SM_A 0
#define SM_B (128 * A_STRIDE)                   // 4608
#define SM_FLOATS (SM_B + BK * B_STRIDE)        // 8960 floats = 35840 B

static __device__ __forceinline__ void split1(float x, uint32_t& h, uint32_t& l) {
    asm("cvt.rna.tf32.f32 %0, %1;" : "=r"(h) : "f"(x));
    float r = x - __uint_as_float(h);   // exact (<=13-bit tail)
    asm("cvt.rna.tf32.f32 %0, %1;" : "=r"(l) : "f"(r));
}

static __device__ __forceinline__ void mma_tf32(
    float& c0, float& c1, float& c2, float& c3,
    uint32_t a0, uint32_t a1, uint32_t a2, uint32_t a3,
    uint32_t b0, uint32_t b1)
{
    asm volatile(
        "mma.sync.aligned.m16n8k8.row.col.f32.tf32.tf32.f32 "
        "{%0,%1,%2,%3}, {%4,%5,%6,%7}, {%8,%9}, {%0,%1,%2,%3};"
        : "+f"(c0), "+f"(c1), "+f"(c2), "+f"(c3)
        : "r"(a0), "r"(a1), "r"(a2), "r"(a3), "r"(b0), "r"(b1));
}

__global__ void __launch_bounds__(256)
triu_gemm_tf32_kernel(const float* __restrict__ A, const float* __restrict__ B,
                      float* __restrict__ C)
{
    const int tj = blockIdx.x;   // output column tile
    const int ti = blockIdx.y;   // output row tile
    const int tid = threadIdx.x;
    const int row0 = ti * TILE;
    const int col0 = tj * TILE;

    // ---- strictly-lower tile: zero-fill only ----
    if (ti > tj) {
        const float4 z = make_float4(0.f, 0.f, 0.f, 0.f);
#pragma unroll
        for (int i = 0; i < 16; ++i) {
            int idx = tid + i * 256;              // 4096 float4s
            int r = idx >> 5, c4 = idx & 31;
            *reinterpret_cast<float4*>(C + (size_t)(row0 + r) * N_DIM + col0 + c4 * 4) = z;
        }
        return;
    }

    __shared__ float sm[SM_FLOATS];
    float* As = sm + SM_A;
    float* Bs = sm + SM_B;

    const int wid  = tid >> 5;
    const int lane = tid & 31;
    const int gid  = lane >> 2;      // 0..7
    const int tig  = lane & 3;       // 0..3
    const int warp_m = wid >> 2;     // 0..1 -> 64-row half
    const int warp_n = wid & 3;      // 0..3 -> 32-col quarter

    float acc[4][4][4];
#pragma unroll
    for (int mt = 0; mt < 4; ++mt)
#pragma unroll
        for (int nt = 0; nt < 4; ++nt)
#pragma unroll
            for (int r = 0; r < 4; ++r) acc[mt][nt][r] = 0.f;

    const int kc0 = ti * (TILE / BK);
    const int kc1 = tj * (TILE / BK) + (TILE / BK) - 1;   // pruned K range

    // A mapping: c = tid + i*256 -> row = c>>3, kgrp = c&7
    // B mapping: c = tid + i*256 -> krow = c>>5, ngrp = c&31
    float4 pa[4], pb[4];
    {
        const int k0 = kc0 * BK;
#pragma unroll
        for (int i = 0; i < 4; ++i) {
            int c = tid + i * 256;
            pa[i] = *reinterpret_cast<const float4*>(
                A + (size_t)(row0 + (c >> 3)) * N_DIM + k0 + (c & 7) * 4);
        }
#pragma unroll
        for (int i = 0; i < 4; ++i) {
            int c = tid + i * 256;
            pb[i] = *reinterpret_cast<const float4*>(
                B + (size_t)(k0 + (c >> 5)) * N_DIM + col0 + (c & 31) * 4);
        }
    }

    for (int kc = kc0; kc <= kc1; ++kc) {
        __syncthreads();   // previous chunk's compute done before overwrite

        // ---- store prefetched fp32 tiles to smem (STS.128, conflict-free) ----
#pragma unroll
        for (int i = 0; i < 4; ++i) {
            int c = tid + i * 256;
            *reinterpret_cast<float4*>(As + (c >> 3) * A_STRIDE + (c & 7) * 4) = pa[i];
        }
#pragma unroll
        for (int i = 0; i < 4; ++i) {
            int c = tid + i * 256;
            *reinterpret_cast<float4*>(Bs + (c >> 5) * B_STRIDE + (c & 31) * 4) = pb[i];
        }

        // ---- prefetch next chunk (overlaps with this chunk's compute) ----
        if (kc < kc1) {
            const int k0n = (kc + 1) * BK;
#pragma unroll
            for (int i = 0; i < 4; ++i) {
                int c = tid + i * 256;
                pa[i] = *reinterpret_cast<const float4*>(
                    A + (size_t)(row0 + (c >> 3)) * N_DIM + k0n + (c & 7) * 4);
            }
#pragma unroll
            for (int i = 0; i < 4; ++i) {
                int c = tid + i * 256;
                pb[i] = *reinterpret_cast<const float4*>(
                    B + (size_t)(k0n + (c >> 5)) * N_DIM + col0 + (c & 31) * 4);
            }
        }

        __syncthreads();

        // ---- compute: 4 k-steps; load fp32 frags once, split, 3 MMA passes ----
#pragma unroll
        for (int ks = 0; ks < 4; ++ks) {
            const int kcol = ks * 8 + tig;
            uint32_t ah[4][4], al[4][4], bh[4][2], bl[4][2];
#pragma unroll
            for (int mt = 0; mt < 4; ++mt) {
                int r = warp_m * 64 + mt * 16 + gid;
                split1(As[r * A_STRIDE + kcol],            ah[mt][0], al[mt][0]);
                split1(As[(r + 8) * A_STRIDE + kcol],      ah[mt][1], al[mt][1]);
                split1(As[r * A_STRIDE + kcol + 4],        ah[mt][2], al[mt][2]);
                split1(As[(r + 8) * A_STRIDE + kcol + 4],  ah[mt][3], al[mt][3]);
            }
#pragma unroll
            for (int nt = 0; nt < 4; ++nt) {
                int cn = warp_n * 32 + nt * 8 + gid;
                split1(Bs[kcol * B_STRIDE + cn],           bh[nt][0], bl[nt][0]);
                split1(Bs[(kcol + 4) * B_STRIDE + cn],     bh[nt][1], bl[nt][1]);
            }
#pragma unroll
            for (int mt = 0; mt < 4; ++mt)
#pragma unroll
                for (int nt = 0; nt < 4; ++nt) {
                    mma_tf32(acc[mt][nt][0], acc[mt][nt][1],
                             acc[mt][nt][2], acc[mt][nt][3],
                             ah[mt][0], ah[mt][1], ah[mt][2], ah[mt][3],
                             bh[nt][0], bh[nt][1]);
                    mma_tf32(acc[mt][nt][0], acc[mt][nt][1],
                             acc[mt][nt][2], acc[mt][nt][3],
                             ah[mt][0], ah[mt][1], ah[mt][2], ah[mt][3],
                             bl[nt][0], bl[nt][1]);
                    mma_tf32(acc[mt][nt][0], acc[mt][nt][1],
                             acc[mt][nt][2], acc[mt][nt][3],
                             al[mt][0], al[mt][1], al[mt][2], al[mt][3],
                             bh[nt][0], bh[nt][1]);
                }
        }
    }

    // ---- epilogue: c0,c1 = (row g, cols 2tig,2tig+1); c2,c3 = row g+8 ----
#pragma unroll
    for (int mt = 0; mt < 4; ++mt) {
        int rbase = row0 + warp_m * 64 + mt * 16 + gid;
#pragma unroll
        for (int nt = 0; nt < 4; ++nt) {
            int cbase = col0 + warp_n * 32 + nt * 8 + tig * 2;
            float2 v0 = make_float2(acc[mt][nt][0], acc[mt][nt][1]);
            float2 v1 = make_float2(acc[mt][nt][2], acc[mt][nt][3]);
            if (ti == tj) {   // triu mask on diagonal tiles
                if (cbase     < rbase)     v0.x = 0.f;
                if (cbase + 1 < rbase)     v0.y = 0.f;
                if (cbase     < rbase + 8) v1.x = 0.f;
                if (cbase + 1 < rbase + 8) v1.y = 0.f;
            }
            *reinterpret_cast<float2*>(C + (size_t)rbase * N_DIM + cbase) = v0;
            *reinterpret_cast<float2*>(C + (size_t)(rbase + 8) * N_DIM + cbase) = v1;
        }
    }
}

extern "C" void kernel_launch(void* const* d_in, const int* in_sizes, int n_in,
                              void* d_out, int out_size) {
    (void)in_sizes; (void)n_in; (void)out_size;
    const float* A = (const float*)d_in[0];
    const float* B = (const float*)d_in[1];
    float* C = (float*)d_out;

    dim3 grid(N_DIM / TILE, N_DIM / TILE);   // x = col tile, y = row tile
    triu_gemm_tf32_kernel<<<grid, 256>>>(A, B, C);
}